// round 10
// baseline (speedup 1.0000x reference)
#include <cuda_runtime.h>
#include <cuda_fp16.h>
#include <cstdint>
#include <cstddef>

// ============================================================================
// KAN layer == fp16 GEMM with 2:4 SPARSE spline block:
//   out[2048,1024] = A[2048,9216] @ Bm[1024,9216]^T
//   A = [ h(x) (K=1024, dense m16n8k16) |
//         one-hot(bin)*w (K=8192, 1-of-8 -> 2:4, mma.sp::ordered_metadata
//         m16n8k32, compressed to K'=4096 + 2-bit metadata) ]
//   Bm = [ h(W) | h(0.1*coeff) ]  (dense, unchanged)
// 80 pipeline steps: 16 dense (A16KB+B16KB) + 64 sparse (Acomp16KB+B32KB).
// ============================================================================

namespace {
constexpr int B_DIM  = 2048;
constexpr int I_DIM  = 1024;
constexpr int O_DIM  = 1024;
constexpr int MT     = 16;                 // 2048 / 128
constexpr int NT     = 8;                  // 1024 / 128
constexpr int STAGES = 4;
constexpr int NSTEP  = 80;                 // 16 dense + 64 sparse supersteps
constexpr int CHUNK_HALVES = 128 * 64;     // [128 rows x 64 fp16] = 16KB
constexpr int CHUNK_BYTES  = CHUNK_HALVES * 2;
constexpr int A_CHUNKS     = 80;           // 16 base + 64 compressed spline
constexpr int B_CHUNKS     = 144;          // 16 base + 128 dense spline
constexpr int STAGE_BYTES  = 3 * CHUNK_BYTES;            // A16KB + B32KB
constexpr int SMEM_TOTAL   = 2048 + STAGES * STAGE_BYTES; // 198656
}  // namespace

// Scratch (__device__ globals; no cudaMalloc allowed).
__device__ __half   g_A   [(size_t)MT * A_CHUNKS * CHUNK_HALVES];  // 21 MB
__device__ __half   g_Bm  [(size_t)NT * B_CHUNKS * CHUNK_HALVES];  // 18.9 MB
// metadata: [mt*8+slab][k32g 0..255][lane-entry 0..15] (entry = quad*2 + t)
__device__ uint32_t g_meta[(size_t)128 * 256 * 16];                // 2 MB

// ---------------------------------------------------------------- helpers --
__device__ __forceinline__ uint32_t smem_u32(const void* p) {
    uint32_t a;
    asm("{ .reg .u64 t; cvta.to.shared.u64 t, %1; cvt.u32.u64 %0, t; }"
        : "=r"(a) : "l"(p));
    return a;
}
__device__ __forceinline__ uint32_t sw128(uint32_t off) {   // Swizzle<3,4,3>
    return off ^ ((off >> 3) & 0x70);
}
__device__ __forceinline__ void mbar_init(uint32_t m, uint32_t cnt) {
    asm volatile("mbarrier.init.shared.b64 [%0], %1;" :: "r"(m), "r"(cnt) : "memory");
}
__device__ __forceinline__ void mbar_expect_tx(uint32_t m, uint32_t bytes) {
    asm volatile("mbarrier.arrive.expect_tx.shared.b64 _, [%0], %1;"
                 :: "r"(m), "r"(bytes) : "memory");
}
__device__ __forceinline__ void mbar_arrive(uint32_t m) {
    asm volatile("mbarrier.arrive.shared.b64 _, [%0];" :: "r"(m) : "memory");
}
__device__ __forceinline__ void mbar_wait(uint32_t m, uint32_t parity) {
    asm volatile(
        "{\n\t.reg .pred P;\n\t"
        "W%=:\n\t"
        "mbarrier.try_wait.parity.acquire.cta.shared::cta.b64 P, [%0], %1, 0x989680;\n\t"
        "@P bra.uni D%=;\n\t"
        "bra.uni W%=;\n\t"
        "D%=:\n\t}"
        :: "r"(m), "r"(parity) : "memory");
}
__device__ __forceinline__ void mbar_wait_relaxed(uint32_t m, uint32_t parity) {
    asm volatile(
        "{\n\t.reg .pred P;\n\t"
        "W%=:\n\t"
        "mbarrier.try_wait.parity.relaxed.cta.shared::cta.b64 P, [%0], %1, 0x989680;\n\t"
        "@P bra.uni D%=;\n\t"
        "bra.uni W%=;\n\t"
        "D%=:\n\t}"
        :: "r"(m), "r"(parity) : "memory");
}
__device__ __forceinline__ void bulk_g2s(uint32_t dst, const void* src,
                                         uint32_t bytes, uint32_t mbar) {
    asm volatile(
        "cp.async.bulk.shared::cluster.global.mbarrier::complete_tx::bytes "
        "[%0], [%1], %2, [%3];"
        :: "r"(dst), "l"(src), "r"(bytes), "r"(mbar) : "memory");
}
__device__ __forceinline__ void mma_f16(float& c0, float& c1, float& c2, float& c3,
                                        uint32_t a0, uint32_t a1, uint32_t a2,
                                        uint32_t a3, uint32_t b0, uint32_t b1) {
    asm volatile(
        "mma.sync.aligned.m16n8k16.row.col.f32.f16.f16.f32 "
        "{%0,%1,%2,%3}, {%4,%5,%6,%7}, {%8,%9}, {%0,%1,%2,%3};"
        : "+f"(c0), "+f"(c1), "+f"(c2), "+f"(c3)
        : "r"(a0), "r"(a1), "r"(a2), "r"(a3), "r"(b0), "r"(b1));
}
__device__ __forceinline__ void mma_sp(float& c0, float& c1, float& c2, float& c3,
                                       uint32_t a0, uint32_t a1, uint32_t a2,
                                       uint32_t a3, uint32_t b0, uint32_t b1,
                                       uint32_t b2, uint32_t b3, uint32_t e) {
    asm volatile(
        "mma.sp::ordered_metadata.sync.aligned.m16n8k32.row.col.f32.f16.f16.f32 "
        "{%0,%1,%2,%3}, {%4,%5,%6,%7}, {%8,%9,%10,%11}, {%0,%1,%2,%3}, %12, 0x0;"
        : "+f"(c0), "+f"(c1), "+f"(c2), "+f"(c3)
        : "r"(a0), "r"(a1), "r"(a2), "r"(a3),
          "r"(b0), "r"(b1), "r"(b2), "r"(b3), "r"(e));
}
__device__ __forceinline__ void ldm_x4(uint32_t* r, uint32_t addr) {
    asm volatile(
        "ldmatrix.sync.aligned.m8n8.x4.shared.b16 {%0,%1,%2,%3}, [%4];"
        : "=r"(r[0]), "=r"(r[1]), "=r"(r[2]), "=r"(r[3]) : "r"(addr));
}
__device__ __forceinline__ uint32_t h2u(__half2 h) {
    return *reinterpret_cast<uint32_t*>(&h);
}
// reference bucketize: grid knots exact 0.25 multiples; bin clamps to 7
__device__ __forceinline__ int bin_of(float x, float& w) {
    const float xc = fminf(1.0f, fmaxf(-1.0f, x));
    const int gi = (xc >= -0.75f) + (xc >= -0.5f) + (xc >= -0.25f) + (xc >= 0.0f) +
                   (xc >=  0.25f) + (xc >=  0.5f) + (xc >=  0.75f);
    w = (xc - (-1.0f + 0.25f * (float)gi)) * 4.0f;
    return gi;
}
// metadata nibble for one 4-group of one i: kept indices (e0,e1)=(p,3)|(0,3)
__device__ __forceinline__ uint32_t meta_byte(float x) {
    float w; const int gi = bin_of(x, w);
    const int grp = gi >> 2, p = gi & 3;
    const uint32_t n0 = 0xCu | ((grp == 0 && p < 3) ? (uint32_t)p : 0u);
    const uint32_t n1 = 0xCu | ((grp == 1 && p < 3) ? (uint32_t)p : 0u);
    return n0 | (n1 << 4);
}

// ------------------------------------------------------------ B builder ----
__global__ void build_B(const float* __restrict__ W, const float* __restrict__ C) {
    const int o  = blockIdx.y;
    const int kg = blockIdx.x * 128 + threadIdx.x;   // 0..1151
    float4 v0, v1;
    if (blockIdx.x == 0) {
        const float4* p = reinterpret_cast<const float4*>(W + (size_t)o * I_DIM + kg * 8);
        v0 = p[0]; v1 = p[1];
    } else {
        const float4* p = reinterpret_cast<const float4*>(C + (size_t)o * 8192 + (kg * 8 - 1024));
        v0 = p[0]; v1 = p[1];
        v0.x *= 0.1f; v0.y *= 0.1f; v0.z *= 0.1f; v0.w *= 0.1f;
        v1.x *= 0.1f; v1.y *= 0.1f; v1.z *= 0.1f; v1.w *= 0.1f;
    }
    uint4 u;
    u.x = h2u(__floats2half2_rn(v0.x, v0.y));
    u.y = h2u(__floats2half2_rn(v0.z, v0.w));
    u.z = h2u(__floats2half2_rn(v1.x, v1.y));
    u.w = h2u(__floats2half2_rn(v1.z, v1.w));
    const int ntile = o >> 7, r = o & 127, ch = kg >> 3;
    char* cb = (char*)(g_Bm + ((size_t)ntile * B_CHUNKS + ch) * CHUNK_HALVES);
    *reinterpret_cast<uint4*>(cb + sw128((uint32_t)(r * 128 + (kg & 7) * 16))) = u;
}

// ------------------------------------------------------------ A builder ----
// base col k=i: h(x); compressed spline: 4 halves per i (2 kept per 4-group).
__global__ void build_A(const float* __restrict__ X) {
    const int idx = blockIdx.x * blockDim.x + threadIdx.x;
    if (idx >= B_DIM * I_DIM) return;
    const int b = idx >> 10, i = idx & 1023;
    const float x = X[idx];
    const int mtile = b >> 7, r = b & 127;
    char* tb = (char*)(g_A + (size_t)mtile * A_CHUNKS * CHUNK_HALVES);

    {   // base: chunk i>>6, half col i&63
        const int ch = i >> 6;
        const uint32_t off = sw128((uint32_t)(r * 128 + (i & 63) * 2));
        *reinterpret_cast<__half*>(tb + (size_t)ch * CHUNK_BYTES + off) =
            __float2half_rn(x);
    }

    float w; const int gi = bin_of(x, w);
    // kept-value slot: group (gi>>2), position 0 unless p==3 (then position 1)
    const int slot = (gi >> 2) * 2 + ((gi & 3) == 3 ? 1 : 0);
    const uint32_t w16 = (uint32_t)__half_as_ushort(__float2half_rn(w));
    uint2 u;
    u.x = (slot < 2) ? (w16 << (slot * 16)) : 0u;
    u.y = (slot >= 2) ? (w16 << ((slot - 2) * 16)) : 0u;

    // compressed col = 4i halves -> chunk 16 + (i>>4), byte col (i&15)*8
    const int ch = 16 + (i >> 4);
    const uint32_t off = sw128((uint32_t)(r * 128 + (i & 15) * 8));
    *reinterpret_cast<uint2*>(tb + (size_t)ch * CHUNK_BYTES + off) = u;
}

// --------------------------------------------------------- meta builder ----
// grid 128 (= mt*8 + slab), 256 threads. Entry (k32g, quad q, t):
//   low16  = row (slab*16+q)  bytes for i = 4*k32g+2t, +1
//   high16 = row (slab*16+q+8) same
__global__ void build_meta(const float* __restrict__ X) {
    extern __shared__ float xs[];            // 16 rows x 1024
    const int blk = blockIdx.x;
    const int mt = blk >> 3, slab = blk & 7;
    const int rowbase = mt * 128 + slab * 16;
    for (int v = threadIdx.x; v < 16 * 1024; v += 256)
        xs[v] = X[(size_t)(rowbase + (v >> 10)) * I_DIM + (v & 1023)];
    __syncthreads();
    for (int e = threadIdx.x; e < 4096; e += 256) {
        const int k32g = e >> 4, q = (e >> 1) & 7, t = e & 1;
        const int i0 = k32g * 4 + 2 * t;
        const float* r0 = xs + q * 1024;
        const float* r1 = xs + (q + 8) * 1024;
        const uint32_t lo = meta_byte(r0[i0]) | (meta_byte(r0[i0 + 1]) << 8);
        const uint32_t hi = meta_byte(r1[i0]) | (meta_byte(r1[i0 + 1]) << 8);
        g_meta[(size_t)blk * 4096 + e] = lo | (hi << 16);
    }
}

// ---------------------------------------------------------------- GEMM -----
// grid (16,8). 8 warps 2(m)x4(n), warp tile 64x32.
// steps 0..15: dense k64 (A16KB+B16KB). steps 16..79: sparse superstep
// (orig k128): Acomp 16KB + B 32KB. Stage = 48KB x 4.
__global__ void __launch_bounds__(256, 1) kan_gemm(float* __restrict__ out) {
    extern __shared__ char smem[];
    const uint32_t sbase = smem_u32(smem);
    const uint32_t hdr   = sbase;
    const uint32_t tiles = (sbase + 2047u) & ~1023u;
    const uint32_t mb_full  = hdr;
    const uint32_t mb_empty = hdr + 64;

    const int tid  = threadIdx.x;
    const int wid  = tid >> 5;
    const int lane = tid & 31;
    const int wm = wid & 1;
    const int wn = wid >> 1;
    const int mt = blockIdx.x, nt = blockIdx.y;

    if (tid == 0) {
        #pragma unroll
        for (int s = 0; s < STAGES; s++) {
            mbar_init(mb_full  + 8 * s, 1);
            mbar_init(mb_empty + 8 * s, 8);
        }
    }
    __syncthreads();

    const __half* gA = g_A  + (size_t)mt * A_CHUNKS * CHUNK_HALVES;
    const __half* gB = g_Bm + (size_t)nt * B_CHUNKS * CHUNK_HALVES;

    // producer lambda-ish: step cc -> stage cc%4
    auto produce = [&](int cc) {
        const int s2 = cc & (STAGES - 1);
        const uint32_t dst = tiles + (uint32_t)s2 * STAGE_BYTES;
        if (cc < 16) {
            mbar_expect_tx(mb_full + 8 * s2, 2 * CHUNK_BYTES);
            bulk_g2s(dst, gA + (size_t)cc * CHUNK_HALVES,
                     CHUNK_BYTES, mb_full + 8 * s2);
            bulk_g2s(dst + CHUNK_BYTES, gB + (size_t)cc * CHUNK_HALVES,
                     CHUNK_BYTES, mb_full + 8 * s2);
        } else {
            mbar_expect_tx(mb_full + 8 * s2, 3 * CHUNK_BYTES);
            bulk_g2s(dst, gA + (size_t)cc * CHUNK_HALVES,
                     CHUNK_BYTES, mb_full + 8 * s2);
            bulk_g2s(dst + CHUNK_BYTES,
                     gB + (size_t)(2 * cc - 16) * CHUNK_HALVES,
                     2 * CHUNK_BYTES, mb_full + 8 * s2);
        }
    };

    if (tid == 0) {
        #pragma unroll
        for (int cc = 0; cc < STAGES - 1; cc++) produce(cc);
    }

    float acc[4][4][4];
    #pragma unroll
    for (int mi = 0; mi < 4; mi++)
        #pragma unroll
        for (int ni = 0; ni < 4; ni++)
            #pragma unroll
            for (int q = 0; q < 4; q++) acc[mi][ni][q] = 0.0f;

    // ldmatrix geometry (SW128, row fixed per lane)
    const uint32_t pat   = (uint32_t)(lane & 7) << 4;
    const uint32_t a_k16 = (uint32_t)((lane >> 4) & 1) << 4;
    const uint32_t b_k16 = (uint32_t)((lane >> 3) & 1) << 4;
    const int a_row_l = ((lane >> 3) & 1) * 8 + (lane & 7);
    const int b_col_l = ((lane >> 4) & 1) * 8 + (lane & 7);
    const uint32_t mlane = (uint32_t)(((lane >> 2) << 1) | (lane & 1));
    const size_t meta_base = ((size_t)(mt * 8 + wm * 4)) * 4096;  // +mi*4096

    for (int n = 0; n < NSTEP; n++) {
        const int s = n & (STAGES - 1);
        if (tid == 0 && n + STAGES - 1 < NSTEP) produce(n + STAGES - 1);
        {   // recycle wait for stage reuse
            // (handled inside produce order: stage s2 reused after 4 steps)
        }
        if (tid == 0) { /* empty-wait folded below */ }

        mbar_wait(mb_full + 8 * s, (n >> 2) & 1);

        const uint32_t As_u = tiles + (uint32_t)s * STAGE_BYTES;
        const uint32_t Bs_u = As_u + CHUNK_BYTES;

        uint32_t abase[4];
        #pragma unroll
        for (int mi = 0; mi < 4; mi++)
            abase[mi] = As_u + (uint32_t)(wm * 64 + mi * 16 + a_row_l) * 128;

        if (n < 16) {
            // ---------------- dense k64 step ----------------
            uint32_t bbase[2];
            #pragma unroll
            for (int p = 0; p < 2; p++)
                bbase[p] = Bs_u + (uint32_t)(wn * 32 + p * 16 + b_col_l) * 128;
            #pragma unroll
            for (int ks = 0; ks < 4; ks++) {
                const uint32_t kb = (uint32_t)(ks * 32);
                uint32_t af[4][4], bf[2][4];
                #pragma unroll
                for (int mi = 0; mi < 4; mi++)
                    ldm_x4(af[mi], abase[mi] + ((kb | a_k16) ^ pat));
                #pragma unroll
                for (int p = 0; p < 2; p++)
                    ldm_x4(bf[p], bbase[p] + ((kb | b_k16) ^ pat));
                #pragma unroll
                for (int mi = 0; mi < 4; mi++)
                    #pragma unroll
                    for (int ni = 0; ni < 4; ni++)
                        mma_f16(acc[mi][ni][0], acc[mi][ni][1],
                                acc[mi][ni][2], acc[mi][ni][3],
                                af[mi][0], af[mi][1], af[mi][2], af[mi][3],
                                bf[ni >> 1][(ni & 1) * 2],
                                bf[ni >> 1][(ni & 1) * 2 + 1]);
            }
        } else {
            // ---------------- sparse superstep (orig k128) ----------------
            const int m = n - 16;
            uint32_t e[4][4];                 // [j][mi]
            #pragma unroll
            for (int j = 0; j < 4; j++)
                #pragma unroll
                for (int mi = 0; mi < 4; mi++)
                    e[j][mi] = g_meta[meta_base + (size_t)mi * 4096 +
                                      (size_t)(m * 4 + j) * 16 + mlane];
            #pragma unroll
            for (int j = 0; j < 4; j++) {
                uint32_t af[4][4];
                #pragma unroll
                for (int mi = 0; mi < 4; mi++)
                    ldm_x4(af[mi], abase[mi] + (((uint32_t)(j * 32) | a_k16) ^ pat));
                const uint32_t bchunk = Bs_u + (uint32_t)(j >> 1) * CHUNK_BYTES;
                uint32_t bb[2];
                #pragma unroll
                for (int p = 0; p < 2; p++)
                    bb[p] = bchunk + (uint32_t)(wn * 32 + p * 16 + b_col_l) * 128;
                const uint32_t kb_lo = (uint32_t)((j & 1) * 64);
                uint32_t bl[2][4], bh[2][4];
                #pragma unroll
                for (int p = 0; p < 2; p++) {
                    ldm_x4(bl[p], bb[p] + ((kb_lo | b_k16) ^ pat));
                    ldm_x4(bh[p], bb[p] + (((kb_lo + 32) | b_k16) ^ pat));
                }
                #pragma unroll
                for (int mi = 0; mi < 4; mi++)
                    #pragma unroll
                    for (int ni = 0; ni < 4; ni++)
                        mma_sp(acc[mi][ni][0], acc[mi][ni][1],
                               acc[mi][ni][2], acc[mi][ni][3],
                               af[mi][0], af[mi][1], af[mi][2], af[mi][3],
                               bl[ni >> 1][(ni & 1) * 2],
                               bl[ni >> 1][(ni & 1) * 2 + 1],
                               bh[ni >> 1][(ni & 1) * 2],
                               bh[ni >> 1][(ni & 1) * 2 + 1],
                               e[j][mi]);
            }
        }

        __syncwarp();
        if (lane == 0) mbar_arrive(mb_empty + 8 * s);
        // producer back-pressure: before reusing a stage, wait its empties
        if (tid == 0 && n + STAGES < NSTEP) {
            const int s2 = (n + STAGES) & (STAGES - 1);   // == s
            mbar_wait_relaxed(mb_empty + 8 * s2, (n >> 2) & 1);
        }
    }

    // ------ epilogue ------
    const int l4 = lane >> 2;
    const int lk = lane & 3;
    const int row0 = mt * 128 + wm * 64 + l4;
    const int col0 = nt * 128 + wn * 32 + 2 * lk;
    #pragma unroll
    for (int mi = 0; mi < 4; mi++) {
        #pragma unroll
        for (int ni = 0; ni < 4; ni++) {
            float* p0 = out + (size_t)(row0 + mi * 16)     * O_DIM + col0 + ni * 8;
            float* p1 = out + (size_t)(row0 + mi * 16 + 8) * O_DIM + col0 + ni * 8;
            *reinterpret_cast<float2*>(p0) =
                make_float2(acc[mi][ni][0], acc[mi][ni][1]);
            *reinterpret_cast<float2*>(p1) =
                make_float2(acc[mi][ni][2], acc[mi][ni][3]);
        }
    }
}

// ---------------------------------------------------------------- launch ---
extern "C" void kernel_launch(void* const* d_in, const int* in_sizes, int n_in,
                              void* d_out, int out_size) {
    (void)in_sizes; (void)n_in; (void)out_size;
    const float* x = (const float*)d_in[0];   // (2048, 1024) fp32
    const float* w = (const float*)d_in[1];   // (1024, 1024) fp32
    const float* c = (const float*)d_in[2];   // (1024, 1024, 8) fp32
    float* out = (float*)d_out;               // (2048, 1024) fp32

    cudaFuncSetAttribute(kan_gemm,
                         cudaFuncAttributeMaxDynamicSharedMemorySize, SMEM_TOTAL);
    cudaFuncSetAttribute(build_meta,
                         cudaFuncAttributeMaxDynamicSharedMemorySize, 65536);

    build_B<<<dim3(9, O_DIM), 128>>>(w, c);
    build_A<<<(B_DIM * I_DIM + 255) / 256, 256>>>(x);
    build_meta<<<128, 256, 65536>>>(x);
    kan_gemm<<<dim3(MT, NT), 256, SMEM_TOTAL>>>(out);
}

// round 11
// speedup vs baseline: 1.0821x; 1.0821x over previous
#include <cuda_runtime.h>
#include <cuda_fp16.h>
#include <cstdint>
#include <cstddef>

// ============================================================================
// KAN layer == fp16 GEMM with 2:4 SPARSE spline block:
//   out[2048,1024] = A[2048,9216] @ Bm[1024,9216]^T
//   A = [ h(x) (K=1024, dense m16n8k16) |
//         one-hot(bin)*w (K=8192, 1-of-8 -> 2:4, mma.sp::ordered_metadata
//         m16n8k32, compressed to K'=4096 + 2-bit metadata) ]
//   Bm = [ h(W) | h(0.1*coeff) ]  (dense)
// R10: 512 threads / 16 warps (4m x 4n, 32x32 warp tile) — the R9 profile
// showed occ=12.3%, tensor=37.7%: latency-bound, not tensor-bound.
// ============================================================================

namespace {
constexpr int B_DIM  = 2048;
constexpr int I_DIM  = 1024;
constexpr int O_DIM  = 1024;
constexpr int MT     = 16;                 // 2048 / 128
constexpr int NT     = 8;                  // 1024 / 128
constexpr int STAGES = 4;
constexpr int NSTEP  = 80;                 // 16 dense + 64 sparse supersteps
constexpr int NWARP  = 16;
constexpr int CHUNK_HALVES = 128 * 64;     // [128 rows x 64 fp16] = 16KB
constexpr int CHUNK_BYTES  = CHUNK_HALVES * 2;
constexpr int A_CHUNKS     = 80;           // 16 base + 64 compressed spline
constexpr int B_CHUNKS     = 144;          // 16 base + 128 dense spline
constexpr int STAGE_BYTES  = 3 * CHUNK_BYTES;             // A16KB + B32KB
constexpr int SMEM_TOTAL   = 2048 + STAGES * STAGE_BYTES; // 198656
}  // namespace

// Scratch (__device__ globals; no cudaMalloc allowed).
__device__ __half   g_A   [(size_t)MT * A_CHUNKS * CHUNK_HALVES];  // 21 MB
__device__ __half   g_Bm  [(size_t)NT * B_CHUNKS * CHUNK_HALVES];  // 18.9 MB
// metadata: [mt*8+slab][k32g 0..255][lane-entry 0..15]
__device__ uint32_t g_meta[(size_t)128 * 256 * 16];                // 2 MB

// ---------------------------------------------------------------- helpers --
__device__ __forceinline__ uint32_t smem_u32(const void* p) {
    uint32_t a;
    asm("{ .reg .u64 t; cvta.to.shared.u64 t, %1; cvt.u32.u64 %0, t; }"
        : "=r"(a) : "l"(p));
    return a;
}
__device__ __forceinline__ uint32_t sw128(uint32_t off) {   // Swizzle<3,4,3>
    return off ^ ((off >> 3) & 0x70);
}
__device__ __forceinline__ void mbar_init(uint32_t m, uint32_t cnt) {
    asm volatile("mbarrier.init.shared.b64 [%0], %1;" :: "r"(m), "r"(cnt) : "memory");
}
__device__ __forceinline__ void mbar_expect_tx(uint32_t m, uint32_t bytes) {
    asm volatile("mbarrier.arrive.expect_tx.shared.b64 _, [%0], %1;"
                 :: "r"(m), "r"(bytes) : "memory");
}
__device__ __forceinline__ void mbar_arrive(uint32_t m) {
    asm volatile("mbarrier.arrive.shared.b64 _, [%0];" :: "r"(m) : "memory");
}
__device__ __forceinline__ void mbar_wait(uint32_t m, uint32_t parity) {
    asm volatile(
        "{\n\t.reg .pred P;\n\t"
        "W%=:\n\t"
        "mbarrier.try_wait.parity.acquire.cta.shared::cta.b64 P, [%0], %1, 0x989680;\n\t"
        "@P bra.uni D%=;\n\t"
        "bra.uni W%=;\n\t"
        "D%=:\n\t}"
        :: "r"(m), "r"(parity) : "memory");
}
__device__ __forceinline__ void mbar_wait_relaxed(uint32_t m, uint32_t parity) {
    asm volatile(
        "{\n\t.reg .pred P;\n\t"
        "W%=:\n\t"
        "mbarrier.try_wait.parity.relaxed.cta.shared::cta.b64 P, [%0], %1, 0x989680;\n\t"
        "@P bra.uni D%=;\n\t"
        "bra.uni W%=;\n\t"
        "D%=:\n\t}"
        :: "r"(m), "r"(parity) : "memory");
}
__device__ __forceinline__ void bulk_g2s(uint32_t dst, const void* src,
                                         uint32_t bytes, uint32_t mbar) {
    asm volatile(
        "cp.async.bulk.shared::cluster.global.mbarrier::complete_tx::bytes "
        "[%0], [%1], %2, [%3];"
        :: "r"(dst), "l"(src), "r"(bytes), "r"(mbar) : "memory");
}
__device__ __forceinline__ void mma_f16(float& c0, float& c1, float& c2, float& c3,
                                        uint32_t a0, uint32_t a1, uint32_t a2,
                                        uint32_t a3, uint32_t b0, uint32_t b1) {
    asm volatile(
        "mma.sync.aligned.m16n8k16.row.col.f32.f16.f16.f32 "
        "{%0,%1,%2,%3}, {%4,%5,%6,%7}, {%8,%9}, {%0,%1,%2,%3};"
        : "+f"(c0), "+f"(c1), "+f"(c2), "+f"(c3)
        : "r"(a0), "r"(a1), "r"(a2), "r"(a3), "r"(b0), "r"(b1));
}
__device__ __forceinline__ void mma_sp(float& c0, float& c1, float& c2, float& c3,
                                       uint32_t a0, uint32_t a1, uint32_t a2,
                                       uint32_t a3, uint32_t b0, uint32_t b1,
                                       uint32_t b2, uint32_t b3, uint32_t e) {
    asm volatile(
        "mma.sp::ordered_metadata.sync.aligned.m16n8k32.row.col.f32.f16.f16.f32 "
        "{%0,%1,%2,%3}, {%4,%5,%6,%7}, {%8,%9,%10,%11}, {%0,%1,%2,%3}, %12, 0x0;"
        : "+f"(c0), "+f"(c1), "+f"(c2), "+f"(c3)
        : "r"(a0), "r"(a1), "r"(a2), "r"(a3),
          "r"(b0), "r"(b1), "r"(b2), "r"(b3), "r"(e));
}
__device__ __forceinline__ void ldm_x4(uint32_t* r, uint32_t addr) {
    asm volatile(
        "ldmatrix.sync.aligned.m8n8.x4.shared.b16 {%0,%1,%2,%3}, [%4];"
        : "=r"(r[0]), "=r"(r[1]), "=r"(r[2]), "=r"(r[3]) : "r"(addr));
}
__device__ __forceinline__ uint32_t h2u(__half2 h) {
    return *reinterpret_cast<uint32_t*>(&h);
}
// reference bucketize: grid knots exact 0.25 multiples; bin clamps to 7
__device__ __forceinline__ int bin_of(float x, float& w) {
    const float xc = fminf(1.0f, fmaxf(-1.0f, x));
    const int gi = (xc >= -0.75f) + (xc >= -0.5f) + (xc >= -0.25f) + (xc >= 0.0f) +
                   (xc >=  0.25f) + (xc >=  0.5f) + (xc >=  0.75f);
    w = (xc - (-1.0f + 0.25f * (float)gi)) * 4.0f;
    return gi;
}
__device__ __forceinline__ uint32_t meta_byte(float x) {
    float w; const int gi = bin_of(x, w);
    const int grp = gi >> 2, p = gi & 3;
    const uint32_t n0 = 0xCu | ((grp == 0 && p < 3) ? (uint32_t)p : 0u);
    const uint32_t n1 = 0xCu | ((grp == 1 && p < 3) ? (uint32_t)p : 0u);
    return n0 | (n1 << 4);
}

// ------------------------------------------------------------ B builder ----
__global__ void build_B(const float* __restrict__ W, const float* __restrict__ C) {
    const int o  = blockIdx.y;
    const int kg = blockIdx.x * 128 + threadIdx.x;   // 0..1151
    float4 v0, v1;
    if (blockIdx.x == 0) {
        const float4* p = reinterpret_cast<const float4*>(W + (size_t)o * I_DIM + kg * 8);
        v0 = p[0]; v1 = p[1];
    } else {
        const float4* p = reinterpret_cast<const float4*>(C + (size_t)o * 8192 + (kg * 8 - 1024));
        v0 = p[0]; v1 = p[1];
        v0.x *= 0.1f; v0.y *= 0.1f; v0.z *= 0.1f; v0.w *= 0.1f;
        v1.x *= 0.1f; v1.y *= 0.1f; v1.z *= 0.1f; v1.w *= 0.1f;
    }
    uint4 u;
    u.x = h2u(__floats2half2_rn(v0.x, v0.y));
    u.y = h2u(__floats2half2_rn(v0.z, v0.w));
    u.z = h2u(__floats2half2_rn(v1.x, v1.y));
    u.w = h2u(__floats2half2_rn(v1.z, v1.w));
    const int ntile = o >> 7, r = o & 127, ch = kg >> 3;
    char* cb = (char*)(g_Bm + ((size_t)ntile * B_CHUNKS + ch) * CHUNK_HALVES);
    *reinterpret_cast<uint4*>(cb + sw128((uint32_t)(r * 128 + (kg & 7) * 16))) = u;
}

// ------------------------------------------------------------ A builder ----
__global__ void build_A(const float* __restrict__ X) {
    const int idx = blockIdx.x * blockDim.x + threadIdx.x;
    if (idx >= B_DIM * I_DIM) return;
    const int b = idx >> 10, i = idx & 1023;
    const float x = X[idx];
    const int mtile = b >> 7, r = b & 127;
    char* tb = (char*)(g_A + (size_t)mtile * A_CHUNKS * CHUNK_HALVES);

    {   // base: chunk i>>6, half col i&63
        const int ch = i >> 6;
        const uint32_t off = sw128((uint32_t)(r * 128 + (i & 63) * 2));
        *reinterpret_cast<__half*>(tb + (size_t)ch * CHUNK_BYTES + off) =
            __float2half_rn(x);
    }

    float w; const int gi = bin_of(x, w);
    const int slot = (gi >> 2) * 2 + ((gi & 3) == 3 ? 1 : 0);
    const uint32_t w16 = (uint32_t)__half_as_ushort(__float2half_rn(w));
    uint2 u;
    u.x = (slot < 2) ? (w16 << (slot * 16)) : 0u;
    u.y = (slot >= 2) ? (w16 << ((slot - 2) * 16)) : 0u;

    const int ch = 16 + (i >> 4);
    const uint32_t off = sw128((uint32_t)(r * 128 + (i & 15) * 8));
    *reinterpret_cast<uint2*>(tb + (size_t)ch * CHUNK_BYTES + off) = u;
}

// --------------------------------------------------------- meta builder ----
__global__ void build_meta(const float* __restrict__ X) {
    extern __shared__ float xs[];            // 16 rows x 1024
    const int blk = blockIdx.x;
    const int mt = blk >> 3, slab = blk & 7;
    const int rowbase = mt * 128 + slab * 16;
    for (int v = threadIdx.x; v < 16 * 1024; v += 256)
        xs[v] = X[(size_t)(rowbase + (v >> 10)) * I_DIM + (v & 1023)];
    __syncthreads();
    for (int e = threadIdx.x; e < 4096; e += 256) {
        const int k32g = e >> 4, q = (e >> 1) & 7, t = e & 1;
        const int i0 = k32g * 4 + 2 * t;
        const float* r0 = xs + q * 1024;
        const float* r1 = xs + (q + 8) * 1024;
        const uint32_t lo = meta_byte(r0[i0]) | (meta_byte(r0[i0 + 1]) << 8);
        const uint32_t hi = meta_byte(r1[i0]) | (meta_byte(r1[i0 + 1]) << 8);
        g_meta[(size_t)blk * 4096 + e] = lo | (hi << 16);
    }
}

// ---------------------------------------------------------------- GEMM -----
// grid (16,8), 512 threads = 16 warps as 4(m) x 4(n); warp tile 32m x 32n.
__global__ void __launch_bounds__(512, 1) kan_gemm(float* __restrict__ out) {
    extern __shared__ char smem[];
    const uint32_t sbase = smem_u32(smem);
    const uint32_t hdr   = sbase;
    const uint32_t tiles = (sbase + 2047u) & ~1023u;
    const uint32_t mb_full  = hdr;
    const uint32_t mb_empty = hdr + 64;

    const int tid  = threadIdx.x;
    const int wid  = tid >> 5;
    const int lane = tid & 31;
    const int wm = wid & 3;                  // m-slab 0..3 (32 rows each)
    const int wn = wid >> 2;                 // n-slab 0..3 (32 cols each)
    const int mt = blockIdx.x, nt = blockIdx.y;

    if (tid == 0) {
        #pragma unroll
        for (int s = 0; s < STAGES; s++) {
            mbar_init(mb_full  + 8 * s, 1);
            mbar_init(mb_empty + 8 * s, NWARP);
        }
    }
    __syncthreads();

    const __half* gA = g_A  + (size_t)mt * A_CHUNKS * CHUNK_HALVES;
    const __half* gB = g_Bm + (size_t)nt * B_CHUNKS * CHUNK_HALVES;

    auto produce = [&](int cc) {
        const int s2 = cc & (STAGES - 1);
        const uint32_t dst = tiles + (uint32_t)s2 * STAGE_BYTES;
        if (cc < 16) {
            mbar_expect_tx(mb_full + 8 * s2, 2 * CHUNK_BYTES);
            bulk_g2s(dst, gA + (size_t)cc * CHUNK_HALVES,
                     CHUNK_BYTES, mb_full + 8 * s2);
            bulk_g2s(dst + CHUNK_BYTES, gB + (size_t)cc * CHUNK_HALVES,
                     CHUNK_BYTES, mb_full + 8 * s2);
        } else {
            mbar_expect_tx(mb_full + 8 * s2, 3 * CHUNK_BYTES);
            bulk_g2s(dst, gA + (size_t)cc * CHUNK_HALVES,
                     CHUNK_BYTES, mb_full + 8 * s2);
            bulk_g2s(dst + CHUNK_BYTES,
                     gB + (size_t)(2 * cc - 16) * CHUNK_HALVES,
                     2 * CHUNK_BYTES, mb_full + 8 * s2);
        }
    };

    if (tid == 0) {
        #pragma unroll
        for (int cc = 0; cc < STAGES - 1; cc++) produce(cc);
    }

    float acc[2][4][4];                      // [mi][ni][frag]
    #pragma unroll
    for (int mi = 0; mi < 2; mi++)
        #pragma unroll
        for (int ni = 0; ni < 4; ni++)
            #pragma unroll
            for (int q = 0; q < 4; q++) acc[mi][ni][q] = 0.0f;

    // ldmatrix geometry (SW128, row fixed per lane)
    const uint32_t pat   = (uint32_t)(lane & 7) << 4;
    const uint32_t a_k16 = (uint32_t)((lane >> 4) & 1) << 4;
    const uint32_t b_k16 = (uint32_t)((lane >> 3) & 1) << 4;
    const int a_row_l = ((lane >> 3) & 1) * 8 + (lane & 7);
    const int b_col_l = ((lane >> 4) & 1) * 8 + (lane & 7);
    const uint32_t mlane = (uint32_t)(((lane >> 2) << 1) | (lane & 1));
    const size_t meta_base = ((size_t)(mt * 8 + wm * 2)) * 4096;   // +mi*4096

    for (int n = 0; n < NSTEP; n++) {
        const int s = n & (STAGES - 1);
        if (tid == 0 && n + STAGES - 1 < NSTEP) produce(n + STAGES - 1);

        mbar_wait(mb_full + 8 * s, (n >> 2) & 1);

        const uint32_t As_u = tiles + (uint32_t)s * STAGE_BYTES;
        const uint32_t Bs_u = As_u + CHUNK_BYTES;

        uint32_t abase[2];
        #pragma unroll
        for (int mi = 0; mi < 2; mi++)
            abase[mi] = As_u + (uint32_t)(wm * 32 + mi * 16 + a_row_l) * 128;

        if (n < 16) {
            // ---------------- dense k64 step ----------------
            uint32_t bbase[2];
            #pragma unroll
            for (int p = 0; p < 2; p++)
                bbase[p] = Bs_u + (uint32_t)(wn * 32 + p * 16 + b_col_l) * 128;
            #pragma unroll
            for (int ks = 0; ks < 4; ks++) {
                const uint32_t kb = (uint32_t)(ks * 32);
                uint32_t af[2][4], bf[2][4];
                #pragma unroll
                for (int mi = 0; mi < 2; mi++)
                    ldm_x4(af[mi], abase[mi] + ((kb | a_k16) ^ pat));
                #pragma unroll
                for (int p = 0; p < 2; p++)
                    ldm_x4(bf[p], bbase[p] + ((kb | b_k16) ^ pat));
                #pragma unroll
                for (int mi = 0; mi < 2; mi++)
                    #pragma unroll
                    for (int ni = 0; ni < 4; ni++)
                        mma_f16(acc[mi][ni][0], acc[mi][ni][1],
                                acc[mi][ni][2], acc[mi][ni][3],
                                af[mi][0], af[mi][1], af[mi][2], af[mi][3],
                                bf[ni >> 1][(ni & 1) * 2],
                                bf[ni >> 1][(ni & 1) * 2 + 1]);
            }
        } else {
            // ---------------- sparse superstep (orig k128) ----------------
            const int m = n - 16;
            uint32_t e[4][2];                 // [j][mi]
            #pragma unroll
            for (int j = 0; j < 4; j++)
                #pragma unroll
                for (int mi = 0; mi < 2; mi++)
                    e[j][mi] = g_meta[meta_base + (size_t)mi * 4096 +
                                      (size_t)(m * 4 + j) * 16 + mlane];
            #pragma unroll
            for (int j = 0; j < 4; j++) {
                uint32_t af[2][4];
                #pragma unroll
                for (int mi = 0; mi < 2; mi++)
                    ldm_x4(af[mi], abase[mi] + (((uint32_t)(j * 32) | a_k16) ^ pat));
                const uint32_t bchunk = Bs_u + (uint32_t)(j >> 1) * CHUNK_BYTES;
                uint32_t bb[2];
                #pragma unroll
                for (int p = 0; p < 2; p++)
                    bb[p] = bchunk + (uint32_t)(wn * 32 + p * 16 + b_col_l) * 128;
                const uint32_t kb_lo = (uint32_t)((j & 1) * 64);
                uint32_t bl[2][4], bh[2][4];
                #pragma unroll
                for (int p = 0; p < 2; p++) {
                    ldm_x4(bl[p], bb[p] + ((kb_lo | b_k16) ^ pat));
                    ldm_x4(bh[p], bb[p] + (((kb_lo + 32) | b_k16) ^ pat));
                }
                #pragma unroll
                for (int mi = 0; mi < 2; mi++)
                    #pragma unroll
                    for (int ni = 0; ni < 4; ni++)
                        mma_sp(acc[mi][ni][0], acc[mi][ni][1],
                               acc[mi][ni][2], acc[mi][ni][3],
                               af[mi][0], af[mi][1], af[mi][2], af[mi][3],
                               bl[ni >> 1][(ni & 1) * 2],
                               bl[ni >> 1][(ni & 1) * 2 + 1],
                               bh[ni >> 1][(ni & 1) * 2],
                               bh[ni >> 1][(ni & 1) * 2 + 1],
                               e[j][mi]);
            }
        }

        __syncwarp();
        if (lane == 0) mbar_arrive(mb_empty + 8 * s);
        if (tid == 0 && n + STAGES < NSTEP) {
            const int s2 = (n + STAGES) & (STAGES - 1);   // == s
            mbar_wait_relaxed(mb_empty + 8 * s2, (n >> 2) & 1);
        }
    }

    // ------ epilogue ------
    const int l4 = lane >> 2;
    const int lk = lane & 3;
    const int row0 = mt * 128 + wm * 32 + l4;
    const int col0 = nt * 128 + wn * 32 + 2 * lk;
    #pragma unroll
    for (int mi = 0; mi < 2; mi++) {
        #pragma unroll
        for (int ni = 0; ni < 4; ni++) {
            float* p0 = out + (size_t)(row0 + mi * 16)     * O_DIM + col0 + ni * 8;
            float* p1 = out + (size_t)(row0 + mi * 16 + 8) * O_DIM + col0 + ni * 8;
            *reinterpret_cast<float2*>(p0) =
                make_float2(acc[mi][ni][0], acc[mi][ni][1]);
            *reinterpret_cast<float2*>(p1) =
                make_float2(acc[mi][ni][2], acc[mi][ni][3]);
        }
    }
}

// ---------------------------------------------------------------- launch ---
extern "C" void kernel_launch(void* const* d_in, const int* in_sizes, int n_in,
                              void* d_out, int out_size) {
    (void)in_sizes; (void)n_in; (void)out_size;
    const float* x = (const float*)d_in[0];   // (2048, 1024) fp32
    const float* w = (const float*)d_in[1];   // (1024, 1024) fp32
    const float* c = (const float*)d_in[2];   // (1024, 1024, 8) fp32
    float* out = (float*)d_out;               // (2048, 1024) fp32

    cudaFuncSetAttribute(kan_gemm,
                         cudaFuncAttributeMaxDynamicSharedMemorySize, SMEM_TOTAL);
    cudaFuncSetAttribute(build_meta,
                         cudaFuncAttributeMaxDynamicSharedMemorySize, 65536);

    build_B<<<dim3(9, O_DIM), 128>>>(w, c);
    build_A<<<(B_DIM * I_DIM + 255) / 256, 256>>>(x);
    build_meta<<<128, 256, 65536>>>(x);
    kan_gemm<<<dim3(MT, NT), 512, SMEM_TOTAL>>>(out);
}